// round 14
// baseline (speedup 1.0000x reference)
#include <cuda_runtime.h>
#include <cuda_bf16.h>
#include <cstdint>
#include <math.h>

// Problem constants
#define S_   2048
#define E_   1024
#define H_   16
#define DH_  64
#define KNB  64
#define E3_  (3*E_)
#define MASKV (-1e10f)

// Scratch (__device__ globals)
__device__ float g_qkv[(size_t)S_ * E3_];
__device__ __nv_bfloat16 g_xh[(size_t)S_ * E_];
__device__ __nv_bfloat16 g_xl[(size_t)S_ * E_];
__device__ __nv_bfloat16 g_wqh[(size_t)E3_ * E_];
__device__ __nv_bfloat16 g_wql[(size_t)E3_ * E_];
__device__ __nv_bfloat16 g_woh[(size_t)E_ * E_];
__device__ __nv_bfloat16 g_wol[(size_t)E_ * E_];
__device__ __nv_bfloat16 g_ah[(size_t)S_ * E_];
__device__ __nv_bfloat16 g_al[(size_t)S_ * E_];

// ---------------------------------------------------------------------------
// helpers
// ---------------------------------------------------------------------------
__device__ __forceinline__ uint32_t smem_u32(const void* p) {
    uint32_t a;
    asm("{ .reg .u64 t; cvta.to.shared.u64 t, %1; cvt.u32.u64 %0, t; }" : "=r"(a) : "l"(p));
    return a;
}
__device__ __forceinline__ uint32_t sw64(uint32_t off) {    // 64B-row swizzle
    return off ^ ((off >> 3) & 0x30);
}
#define LDSM4(r, a) \
    asm volatile("ldmatrix.sync.aligned.m8n8.x4.shared.b16 {%0,%1,%2,%3}, [%4];" \
        : "=r"((r)[0]), "=r"((r)[1]), "=r"((r)[2]), "=r"((r)[3]) : "r"(a))

__device__ __forceinline__ void mma16816(float* d, const uint32_t* a, const uint32_t* b) {
    asm volatile("mma.sync.aligned.m16n8k16.row.col.f32.bf16.bf16.f32 "
        "{%0,%1,%2,%3}, {%4,%5,%6,%7}, {%8,%9}, {%0,%1,%2,%3};"
        : "+f"(d[0]), "+f"(d[1]), "+f"(d[2]), "+f"(d[3])
        : "r"(a[0]), "r"(a[1]), "r"(a[2]), "r"(a[3]), "r"(b[0]), "r"(b[1]));
}
#define CP_ASYNC16(dst, src) \
    asm volatile("cp.async.cg.shared.global [%0], [%1], 16;" :: "r"(dst), "l"(src))
#define CP_COMMIT() asm volatile("cp.async.commit_group;" ::: "memory")
#define CP_WAIT0()  asm volatile("cp.async.wait_group 0;" ::: "memory")

// ---------------------------------------------------------------------------
// fused split kernel: fp32 -> bf16 hi + bf16 lo for x, W_qkv, W_out
// ---------------------------------------------------------------------------
#define NX4  ((S_ * E_) / 4)
#define NWQ4 ((E3_ * E_) / 4)
#define NWO4 ((E_ * E_) / 4)
#define NSPLIT4 (NX4 + NWQ4 + NWO4)

__device__ __forceinline__ void split_one(const float4* in, uint2* hi, uint2* lo, int i) {
    float4 v = in[i];
    __nv_bfloat162 h0 = __float22bfloat162_rn(make_float2(v.x, v.y));
    __nv_bfloat162 h1 = __float22bfloat162_rn(make_float2(v.z, v.w));
    float2 f0 = __bfloat1622float2(h0);
    float2 f1 = __bfloat1622float2(h1);
    __nv_bfloat162 l0 = __float22bfloat162_rn(make_float2(v.x - f0.x, v.y - f0.y));
    __nv_bfloat162 l1 = __float22bfloat162_rn(make_float2(v.z - f1.x, v.w - f1.y));
    uint2 h, l;
    h.x = *(uint32_t*)&h0; h.y = *(uint32_t*)&h1;
    l.x = *(uint32_t*)&l0; l.y = *(uint32_t*)&l1;
    hi[i] = h;
    lo[i] = l;
}

__global__ __launch_bounds__(256)
void split_all(const float4* __restrict__ x, const float4* __restrict__ wq,
               const float4* __restrict__ wo,
               uint2* __restrict__ xh, uint2* __restrict__ xl,
               uint2* __restrict__ wqh, uint2* __restrict__ wql,
               uint2* __restrict__ woh, uint2* __restrict__ wol)
{
    int i = blockIdx.x * 256 + threadIdx.x;
    if (i < NX4) {
        split_one(x, xh, xl, i);
    } else if (i < NX4 + NWQ4) {
        split_one(wq, wqh, wql, i - NX4);
    } else if (i < NSPLIT4) {
        split_one(wo, woh, wol, i - NX4 - NWQ4);
    }
}

// ---------------------------------------------------------------------------
// bf16-split tensor GEMM (NT): C[M,N] = A[M,K] @ B[N,K]^T + bias[N]
// Tile 128x64x32, 256 threads, 3 CTAs/SM, double-buffered cp.async,
// single barrier per chunk, SW64 smem (64B rows).
// ---------------------------------------------------------------------------
#define ATILEB 8192                  // 128 x 32 bf16
#define BTILEB 4096                  // 64 x 32 bf16
#define STAGEB (2 * ATILEB + 2 * BTILEB)   // 24576
#define GSMEM  (2 * STAGEB)                // 49152

__global__ __launch_bounds__(256, 3)
void bf16s_gemm_nt_bias(const __nv_bfloat16* __restrict__ Ah,
                        const __nv_bfloat16* __restrict__ Al,
                        const __nv_bfloat16* __restrict__ Bh,
                        const __nv_bfloat16* __restrict__ Bl,
                        const float* __restrict__ bias, float* __restrict__ C,
                        int M, int N, int K)
{
    extern __shared__ char sm[];
    const uint32_t sbase = smem_u32(sm);

    const int tid  = threadIdx.x;
    const int lane = tid & 31;
    const int wid  = tid >> 5;
    const int wm   = (wid & 3) * 32;
    const int wn   = (wid >> 2) * 32;
    const int m0   = blockIdx.y * 128;
    const int n0   = blockIdx.x * 64;

    const __nv_bfloat16* abase[2] = { Ah + (size_t)m0 * K, Al + (size_t)m0 * K };
    const __nv_bfloat16* bbase[2] = { Bh + (size_t)n0 * K, Bl + (size_t)n0 * K };

    float d[2][4][4];
#pragma unroll
    for (int i = 0; i < 2; i++)
#pragma unroll
        for (int j = 0; j < 4; j++)
#pragma unroll
            for (int q = 0; q < 4; q++) d[i][j][q] = 0.f;

    auto issue = [&](int c) {
        const int s = c & 1;
        const int k0 = c * 32;
        const uint32_t sb = sbase + s * STAGEB;
        // A tiles: 2 x 512 chunks -> 4 per thread
#pragma unroll
        for (int l = 0; l < 4; l++) {
            const int idx  = l * 256 + tid;          // 0..1023
            const int tile = idx >> 9;
            const int w512 = idx & 511;
            const int row  = w512 >> 2;              // 0..127
            const int q    = w512 & 3;
            const __nv_bfloat16* src = abase[tile] + (size_t)row * K + k0 + q * 8;
            const uint32_t dst = sb + tile * ATILEB + sw64(row * 64 + q * 16);
            CP_ASYNC16(dst, src);
        }
        // B tiles: 2 x 256 chunks -> 2 per thread
#pragma unroll
        for (int l = 0; l < 2; l++) {
            const int idx  = l * 256 + tid;          // 0..511
            const int tile = idx >> 8;
            const int w256 = idx & 255;
            const int row  = w256 >> 2;              // 0..63
            const int q    = w256 & 3;
            const __nv_bfloat16* src = bbase[tile] + (size_t)row * K + k0 + q * 8;
            const uint32_t dst = sb + 2 * ATILEB + tile * BTILEB
                               + sw64(row * 64 + q * 16);
            CP_ASYNC16(dst, src);
        }
        CP_COMMIT();
    };

    // hoisted ldmatrix base offsets (sw64(row*64+colb) = sw64(row*64)^colb, colb<64)
    uint32_t baseA[2], baseB[2];
#pragma unroll
    for (int i = 0; i < 2; i++) {
        uint32_t ra = (uint32_t)(wm + i * 16 + (lane & 15));
        baseA[i] = (ra * 64) ^ ((ra * 8) & 0x30);
        uint32_t rb = (uint32_t)(wn + i * 16 + (lane & 15));
        baseB[i] = (rb * 64) ^ ((rb * 8) & 0x30);
    }
    const uint32_t lanecol = (uint32_t)((lane >> 4) << 4);

    auto compute = [&](int s) {
        const uint32_t sb = sbase + s * STAGEB;
#pragma unroll
        for (int ks = 0; ks < 2; ks++) {
            const uint32_t colb = (uint32_t)(ks * 32) ^ lanecol;

            uint32_t bh[4][2], bl[4][2];
#pragma unroll
            for (int ng = 0; ng < 2; ng++) {
                uint32_t off = baseB[ng] ^ colb;
                uint32_t r[4];
                LDSM4(r, sb + 2 * ATILEB + off);
                bh[ng * 2 + 0][0] = r[0]; bh[ng * 2 + 0][1] = r[2];
                bh[ng * 2 + 1][0] = r[1]; bh[ng * 2 + 1][1] = r[3];
                LDSM4(r, sb + 2 * ATILEB + BTILEB + off);
                bl[ng * 2 + 0][0] = r[0]; bl[ng * 2 + 0][1] = r[2];
                bl[ng * 2 + 1][0] = r[1]; bl[ng * 2 + 1][1] = r[3];
            }

#pragma unroll
            for (int mt = 0; mt < 2; mt++) {
                uint32_t off = baseA[mt] ^ colb;
                uint32_t ah[4], al[4];
                LDSM4(ah, sb + off);
                LDSM4(al, sb + ATILEB + off);
#pragma unroll
                for (int nt = 0; nt < 4; nt++) {
                    mma16816(d[mt][nt], ah, bh[nt]);
                    mma16816(d[mt][nt], ah, bl[nt]);
                    mma16816(d[mt][nt], al, bh[nt]);
                }
            }
        }
    };

    const int NC = K / 32;
    issue(0);
    for (int c = 0; c < NC; c++) {
        CP_WAIT0();
        __syncthreads();
        if (c + 1 < NC) issue(c + 1);
        compute(c & 1);
    }

    // epilogue
#pragma unroll
    for (int mt = 0; mt < 2; mt++) {
        const int r0 = m0 + wm + mt * 16 + (lane >> 2);
#pragma unroll
        for (int nt = 0; nt < 4; nt++) {
            const int c0 = n0 + wn + nt * 8 + (lane & 3) * 2;
            const float b0 = bias[c0], b1 = bias[c0 + 1];
            float2 o;
            o.x = d[mt][nt][0] + b0;
            o.y = d[mt][nt][1] + b1;
            *(float2*)(C + (size_t)r0 * N + c0) = o;
            o.x = d[mt][nt][2] + b0;
            o.y = d[mt][nt][3] + b1;
            *(float2*)(C + (size_t)(r0 + 8) * N + c0) = o;
        }
    }
}

// ---------------------------------------------------------------------------
// Banded scores + softmax + attn@V — TI=16, interchanged QK loop (R11, proven)
// ---------------------------------------------------------------------------
#define TI    16
#define NUMAX 144
#define KVST  68
#define NT    256

__global__ __launch_bounds__(NT)
void scores_attn_kernel(const float* __restrict__ qkv,
                        float* __restrict__ scores_out,
                        __nv_bfloat16* __restrict__ attn_hi,
                        __nv_bfloat16* __restrict__ attn_lo)
{
    __shared__ float KVs[NUMAX * KVST];
    __shared__ float Qs[TI * KVST];
    __shared__ float Sc[TI * NUMAX];

    const int h  = blockIdx.y;
    const int i0 = blockIdx.x * TI;
    const int t  = threadIdx.x;

    const int j0 = max(0, i0 - KNB);
    const int j1 = min(S_ - 1, i0 + TI - 1 + KNB);
    const int NU = j1 - j0 + 1;           // <= 144

    const int hoff = h * DH_;

    for (int idx = t; idx < TI * 16; idx += NT) {
        int r = idx >> 4, dq = idx & 15;
        *(float4*)(Qs + r * KVST + dq * 4) =
            *(const float4*)(qkv + (size_t)(i0 + r) * E3_ + hoff + dq * 4);
    }
    for (int idx = t; idx < NU * 16; idx += NT) {
        int u = idx >> 4, dq = idx & 15;
        *(float4*)(KVs + u * KVST + dq * 4) =
            *(const float4*)(qkv + (size_t)(j0 + u) * E3_ + E_ + hoff + dq * 4);
    }
    __syncthreads();

    if (t < NU) {
        const int j = j0 + t;
        const float4* kv4 = (const float4*)(KVs + t * KVST);
        float acc[TI];
#pragma unroll
        for (int r = 0; r < TI; r++) acc[r] = 0.f;
#pragma unroll
        for (int dq = 0; dq < 16; dq++) {
            const float4 b = kv4[dq];
#pragma unroll
            for (int r = 0; r < TI; r++) {
                const float4 a = *(const float4*)(Qs + r * KVST + dq * 4);
                acc[r] = fmaf(a.x, b.x, acc[r]);
                acc[r] = fmaf(a.y, b.y, acc[r]);
                acc[r] = fmaf(a.z, b.z, acc[r]);
                acc[r] = fmaf(a.w, b.w, acc[r]);
            }
        }
#pragma unroll
        for (int r = 0; r < TI; r++) {
            const int i = i0 + r;
            Sc[r * NUMAX + t] =
                (abs(i - j) <= KNB) ? acc[r] * 0.125f : -INFINITY;
        }
    }
    __syncthreads();

    for (int idx = t; idx < NU * 16; idx += NT) {
        int u = idx >> 4, dq = idx & 15;
        *(float4*)(KVs + u * KVST + dq * 4) =
            *(const float4*)(qkv + (size_t)(j0 + u) * E3_ + 2 * E_ + hoff + dq * 4);
    }

#pragma unroll
    for (int r = 0; r < TI; r++) {
        const int i = i0 + r;
        const int lo = i - KNB, hi = i + KNB;
        float* rowp = scores_out + ((size_t)h * S_ + i) * S_;
#pragma unroll
        for (int it = 0; it < S_ / (NT * 4); it++) {
            const int j = (it * NT + t) * 4;
            float4 v;
            v.x = (j + 0 >= lo && j + 0 <= hi) ? Sc[r * NUMAX + (j + 0 - j0)] : MASKV;
            v.y = (j + 1 >= lo && j + 1 <= hi) ? Sc[r * NUMAX + (j + 1 - j0)] : MASKV;
            v.z = (j + 2 >= lo && j + 2 <= hi) ? Sc[r * NUMAX + (j + 2 - j0)] : MASKV;
            v.w = (j + 3 >= lo && j + 3 <= hi) ? Sc[r * NUMAX + (j + 3 - j0)] : MASKV;
            __stcs((float4*)(rowp + j), v);
        }
    }
    __syncthreads();

    const int w = t >> 5, lane = t & 31;
#pragma unroll
    for (int rr = 0; rr < 2; rr++) {
        const int r = w * 2 + rr;
        float m = -INFINITY;
        for (int u = lane; u < NU; u += 32)
            m = fmaxf(m, Sc[r * NUMAX + u]);
#pragma unroll
        for (int o = 16; o; o >>= 1)
            m = fmaxf(m, __shfl_xor_sync(0xFFFFFFFFu, m, o));
        float ssum = 0.f;
        for (int u = lane; u < NU; u += 32) {
            float e = expf(Sc[r * NUMAX + u] - m);
            Sc[r * NUMAX + u] = e;
            ssum += e;
        }
#pragma unroll
        for (int o = 16; o; o >>= 1)
            ssum += __shfl_xor_sync(0xFFFFFFFFu, ssum, o);
        float inv = 1.f / ssum;
        for (int u = lane; u < NU; u += 32)
            Sc[r * NUMAX + u] *= inv;
    }
    __syncthreads();

    {
        const int r  = t >> 4;
        const int dg = t & 15;
        const float* pr = Sc + r * NUMAX;
        float4 acc = make_float4(0.f, 0.f, 0.f, 0.f);
        for (int u = 0; u < NU; u++) {
            const float p = pr[u];
            const float4 v = *(const float4*)(KVs + u * KVST + dg * 4);
            acc.x = fmaf(p, v.x, acc.x);
            acc.y = fmaf(p, v.y, acc.y);
            acc.z = fmaf(p, v.z, acc.z);
            acc.w = fmaf(p, v.w, acc.w);
        }
        __nv_bfloat162 h01 = __float22bfloat162_rn(make_float2(acc.x, acc.y));
        __nv_bfloat162 h23 = __float22bfloat162_rn(make_float2(acc.z, acc.w));
        float2 f01 = __bfloat1622float2(h01);
        float2 f23 = __bfloat1622float2(h23);
        __nv_bfloat162 l01 = __float22bfloat162_rn(make_float2(acc.x - f01.x, acc.y - f01.y));
        __nv_bfloat162 l23 = __float22bfloat162_rn(make_float2(acc.z - f23.x, acc.w - f23.y));
        const size_t idx = (size_t)(i0 + r) * E_ + hoff + dg * 4;
        uint2 hv, lv;
        hv.x = *(uint32_t*)&h01; hv.y = *(uint32_t*)&h23;
        lv.x = *(uint32_t*)&l01; lv.y = *(uint32_t*)&l23;
        *(uint2*)(attn_hi + idx) = hv;
        *(uint2*)(attn_lo + idx) = lv;
    }
}

// ---------------------------------------------------------------------------
// launch
// ---------------------------------------------------------------------------
extern "C" void kernel_launch(void* const* d_in, const int* in_sizes, int n_in,
                              void* d_out, int out_size)
{
    const float* x     = (const float*)d_in[0];
    const float* W_qkv = (const float*)d_in[1];
    const float* b_qkv = (const float*)d_in[2];
    const float* W_out = (const float*)d_in[3];
    const float* b_out = (const float*)d_in[4];

    float* out_ptr    = (float*)d_out;
    float* scores_ptr = out_ptr + (size_t)S_ * E_;

    float* qkv_p;
    __nv_bfloat16 *xh, *xl, *wqh, *wql, *woh, *wol, *ah, *al;
    cudaGetSymbolAddress((void**)&qkv_p, g_qkv);
    cudaGetSymbolAddress((void**)&xh,  g_xh);
    cudaGetSymbolAddress((void**)&xl,  g_xl);
    cudaGetSymbolAddress((void**)&wqh, g_wqh);
    cudaGetSymbolAddress((void**)&wql, g_wql);
    cudaGetSymbolAddress((void**)&woh, g_woh);
    cudaGetSymbolAddress((void**)&wol, g_wol);
    cudaGetSymbolAddress((void**)&ah,  g_ah);
    cudaGetSymbolAddress((void**)&al,  g_al);

    cudaFuncSetAttribute(bf16s_gemm_nt_bias,
                         cudaFuncAttributeMaxDynamicSharedMemorySize, GSMEM);

    // fused splits
    split_all<<<(NSPLIT4 + 255) / 256, 256>>>(
        (const float4*)x, (const float4*)W_qkv, (const float4*)W_out,
        (uint2*)xh, (uint2*)xl, (uint2*)wqh, (uint2*)wql, (uint2*)woh, (uint2*)wol);

    // 1) QKV projection
    {
        dim3 grid(E3_ / 64, S_ / 128);
        bf16s_gemm_nt_bias<<<grid, 256, GSMEM>>>(xh, xl, wqh, wql, b_qkv, qkv_p,
                                                 S_, E3_, E_);
    }

    // 2) banded scores + softmax + attn@V
    {
        dim3 grid(S_ / TI, H_);
        scores_attn_kernel<<<grid, NT>>>(qkv_p, scores_ptr, ah, al);
    }

    // 3) output projection
    {
        dim3 grid(E_ / 64, S_ / 128);
        bf16s_gemm_nt_bias<<<grid, 256, GSMEM>>>(ah, al, woh, wol, b_out, out_ptr,
                                                 S_, E_, E_);
    }
}

// round 15
// speedup vs baseline: 1.0239x; 1.0239x over previous
#include <cuda_runtime.h>
#include <cuda_bf16.h>
#include <cstdint>
#include <math.h>

// Problem constants
#define S_   2048
#define E_   1024
#define H_   16
#define DH_  64
#define KNB  64
#define E3_  (3*E_)
#define MASKV (-1e10f)

// Scratch (__device__ globals)
__device__ float g_qkv[(size_t)S_ * E3_];
__device__ __nv_bfloat16 g_xh[(size_t)S_ * E_];
__device__ __nv_bfloat16 g_xl[(size_t)S_ * E_];
__device__ __nv_bfloat16 g_wqh[(size_t)E3_ * E_];
__device__ __nv_bfloat16 g_wql[(size_t)E3_ * E_];
__device__ __nv_bfloat16 g_woh[(size_t)E_ * E_];
__device__ __nv_bfloat16 g_wol[(size_t)E_ * E_];
__device__ __nv_bfloat16 g_ah[(size_t)S_ * E_];
__device__ __nv_bfloat16 g_al[(size_t)S_ * E_];

// ---------------------------------------------------------------------------
// helpers
// ---------------------------------------------------------------------------
__device__ __forceinline__ uint32_t smem_u32(const void* p) {
    uint32_t a;
    asm("{ .reg .u64 t; cvta.to.shared.u64 t, %1; cvt.u32.u64 %0, t; }" : "=r"(a) : "l"(p));
    return a;
}
__device__ __forceinline__ uint32_t sw128(uint32_t off) {
    return off ^ ((off >> 3) & 0x70);
}
#define LDSM4(r, a) \
    asm volatile("ldmatrix.sync.aligned.m8n8.x4.shared.b16 {%0,%1,%2,%3}, [%4];" \
        : "=r"((r)[0]), "=r"((r)[1]), "=r"((r)[2]), "=r"((r)[3]) : "r"(a))

__device__ __forceinline__ void mma16816(float* d, const uint32_t* a, const uint32_t* b) {
    asm volatile("mma.sync.aligned.m16n8k16.row.col.f32.bf16.bf16.f32 "
        "{%0,%1,%2,%3}, {%4,%5,%6,%7}, {%8,%9}, {%0,%1,%2,%3};"
        : "+f"(d[0]), "+f"(d[1]), "+f"(d[2]), "+f"(d[3])
        : "r"(a[0]), "r"(a[1]), "r"(a[2]), "r"(a[3]), "r"(b[0]), "r"(b[1]));
}
#define CP_ASYNC16(dst, src) \
    asm volatile("cp.async.cg.shared.global [%0], [%1], 16;" :: "r"(dst), "l"(src))
#define CP_COMMIT() asm volatile("cp.async.commit_group;" ::: "memory")
#define CP_WAIT0()  asm volatile("cp.async.wait_group 0;" ::: "memory")

// ---------------------------------------------------------------------------
// fused split kernel: fp32 -> bf16 hi + bf16 lo for x, W_qkv, W_out
// ---------------------------------------------------------------------------
#define NX4  ((S_ * E_) / 4)
#define NWQ4 ((E3_ * E_) / 4)
#define NWO4 ((E_ * E_) / 4)
#define NSPLIT4 (NX4 + NWQ4 + NWO4)

__device__ __forceinline__ void split_one(const float4* in, uint2* hi, uint2* lo, int i) {
    float4 v = in[i];
    __nv_bfloat162 h0 = __float22bfloat162_rn(make_float2(v.x, v.y));
    __nv_bfloat162 h1 = __float22bfloat162_rn(make_float2(v.z, v.w));
    float2 f0 = __bfloat1622float2(h0);
    float2 f1 = __bfloat1622float2(h1);
    __nv_bfloat162 l0 = __float22bfloat162_rn(make_float2(v.x - f0.x, v.y - f0.y));
    __nv_bfloat162 l1 = __float22bfloat162_rn(make_float2(v.z - f1.x, v.w - f1.y));
    uint2 h, l;
    h.x = *(uint32_t*)&h0; h.y = *(uint32_t*)&h1;
    l.x = *(uint32_t*)&l0; l.y = *(uint32_t*)&l1;
    hi[i] = h;
    lo[i] = l;
}

__global__ __launch_bounds__(256)
void split_all(const float4* __restrict__ x, const float4* __restrict__ wq,
               const float4* __restrict__ wo,
               uint2* __restrict__ xh, uint2* __restrict__ xl,
               uint2* __restrict__ wqh, uint2* __restrict__ wql,
               uint2* __restrict__ woh, uint2* __restrict__ wol)
{
    int i = blockIdx.x * 256 + threadIdx.x;
    if (i < NX4) {
        split_one(x, xh, xl, i);
    } else if (i < NX4 + NWQ4) {
        split_one(wq, wqh, wql, i - NX4);
    } else if (i < NSPLIT4) {
        split_one(wo, woh, wol, i - NX4 - NWQ4);
    }
}

// ---------------------------------------------------------------------------
// bf16-split tensor GEMM (NT) + optional fused mask-fill tail.
// Tile 128x64x64, 256 threads, 2 CTAs/SM, double-buffered cp.async,
// single barrier per chunk, B-fragment double-buffer across ks. (R13 proven)
// ---------------------------------------------------------------------------
#define ATILEB 16384
#define BTILEB 8192
#define STAGEB (2 * ATILEB + 2 * BTILEB)     // 49152
#define GSMEM  (2 * STAGEB)                  // 98304
#define NSC4   ((H_ * S_ * S_) / 4)          // 16777216 float4 in scores

__global__ __launch_bounds__(256, 2)
void bf16s_gemm_nt_bias(const __nv_bfloat16* __restrict__ Ah,
                        const __nv_bfloat16* __restrict__ Al,
                        const __nv_bfloat16* __restrict__ Bh,
                        const __nv_bfloat16* __restrict__ Bl,
                        const float* __restrict__ bias, float* __restrict__ C,
                        int M, int N, int K,
                        float4* __restrict__ fill_ptr)   // null = no fill
{
    extern __shared__ char sm[];
    const uint32_t sbase = smem_u32(sm);

    const int tid  = threadIdx.x;
    const int lane = tid & 31;
    const int wid  = tid >> 5;
    const int wm   = (wid & 3) * 32;
    const int wn   = (wid >> 2) * 32;
    const int m0   = blockIdx.y * 128;
    const int n0   = blockIdx.x * 64;

    const __nv_bfloat16* abase[2] = { Ah + (size_t)m0 * K, Al + (size_t)m0 * K };
    const __nv_bfloat16* bbase[2] = { Bh + (size_t)n0 * K, Bl + (size_t)n0 * K };

    float d[2][4][4];
#pragma unroll
    for (int i = 0; i < 2; i++)
#pragma unroll
        for (int j = 0; j < 4; j++)
#pragma unroll
            for (int q = 0; q < 4; q++) d[i][j][q] = 0.f;

    auto issue = [&](int c) {
        const int s = c & 1;
        const int k0 = c * 64;
        const uint32_t sb = sbase + s * STAGEB;
#pragma unroll
        for (int i = 0; i < 8; i++) {
            const int tile = i >> 2;
            const int idx  = (i & 3) * 256 + tid;
            const int row  = idx >> 3;
            const int q    = idx & 7;
            const __nv_bfloat16* src = abase[tile] + (size_t)row * K + k0 + q * 8;
            const uint32_t dst = sb + tile * ATILEB + sw128(row * 128 + q * 16);
            CP_ASYNC16(dst, src);
        }
#pragma unroll
        for (int i = 0; i < 4; i++) {
            const int tile = i >> 1;
            const int idx  = (i & 1) * 256 + tid;
            const int row  = idx >> 3;
            const int q    = idx & 7;
            const __nv_bfloat16* src = bbase[tile] + (size_t)row * K + k0 + q * 8;
            const uint32_t dst = sb + 2 * ATILEB + tile * BTILEB
                               + sw128(row * 128 + q * 16);
            CP_ASYNC16(dst, src);
        }
        CP_COMMIT();
    };

    uint32_t baseA[2], baseB[2];
#pragma unroll
    for (int i = 0; i < 2; i++) {
        uint32_t ra = (uint32_t)(wm + i * 16 + (lane & 15));
        baseA[i] = (ra * 128) ^ ((ra * 16) & 0x70);
        uint32_t rb = (uint32_t)(wn + i * 16 + (lane & 15));
        baseB[i] = (rb * 128) ^ ((rb * 16) & 0x70);
    }
    const uint32_t lanecol = (uint32_t)((lane >> 4) << 4);

    auto loadB = [&](uint32_t sb, int ks, uint32_t (*bh)[2], uint32_t (*bl)[2]) {
        const uint32_t colb = (uint32_t)(ks * 32) ^ lanecol;
#pragma unroll
        for (int ng = 0; ng < 2; ng++) {
            uint32_t off = baseB[ng] ^ colb;
            uint32_t r[4];
            LDSM4(r, sb + 2 * ATILEB + off);
            bh[ng * 2 + 0][0] = r[0]; bh[ng * 2 + 0][1] = r[2];
            bh[ng * 2 + 1][0] = r[1]; bh[ng * 2 + 1][1] = r[3];
            LDSM4(r, sb + 2 * ATILEB + BTILEB + off);
            bl[ng * 2 + 0][0] = r[0]; bl[ng * 2 + 0][1] = r[2];
            bl[ng * 2 + 1][0] = r[1]; bl[ng * 2 + 1][1] = r[3];
        }
    };

    auto compute = [&](int s) {
        const uint32_t sb = sbase + s * STAGEB;
        uint32_t bh[2][4][2], bl[2][4][2];
        loadB(sb, 0, bh[0], bl[0]);
#pragma unroll
        for (int ks = 0; ks < 4; ks++) {
            const int cur = ks & 1;
            if (ks < 3) loadB(sb, ks + 1, bh[cur ^ 1], bl[cur ^ 1]);

            const uint32_t colb = (uint32_t)(ks * 32) ^ lanecol;
#pragma unroll
            for (int mt = 0; mt < 2; mt++) {
                uint32_t off = baseA[mt] ^ colb;
                uint32_t ah[4], al[4];
                LDSM4(ah, sb + off);
                LDSM4(al, sb + ATILEB + off);
#pragma unroll
                for (int nt = 0; nt < 4; nt++) {
                    mma16816(d[mt][nt], ah, bh[cur][nt]);
                    mma16816(d[mt][nt], ah, bl[cur][nt]);
                    mma16816(d[mt][nt], al, bh[cur][nt]);
                }
            }
        }
    };

    const int NC = K / 64;
    issue(0);
    for (int c = 0; c < NC; c++) {
        CP_WAIT0();
        __syncthreads();
        if (c + 1 < NC) issue(c + 1);
        compute(c & 1);
    }

    // epilogue
#pragma unroll
    for (int mt = 0; mt < 2; mt++) {
        const int r0 = m0 + wm + mt * 16 + (lane >> 2);
#pragma unroll
        for (int nt = 0; nt < 4; nt++) {
            const int c0 = n0 + wn + nt * 8 + (lane & 3) * 2;
            const float b0 = bias[c0], b1 = bias[c0 + 1];
            float2 o;
            o.x = d[mt][nt][0] + b0;
            o.y = d[mt][nt][1] + b1;
            *(float2*)(C + (size_t)r0 * N + c0) = o;
            o.x = d[mt][nt][2] + b0;
            o.y = d[mt][nt][3] + b1;
            *(float2*)(C + (size_t)(r0 + 8) * N + c0) = o;
        }
    }

    // fused mask-fill tail (QKV GEMM only): streaming stores through the
    // otherwise-idle DRAM; early CTAs' fill overlaps later waves' compute.
    if (fill_ptr) {
        const int nblk = gridDim.x * gridDim.y;
        const int bid  = blockIdx.y * gridDim.x + blockIdx.x;
        const float4 mv = make_float4(MASKV, MASKV, MASKV, MASKV);
        for (int i = bid * 256 + tid; i < NSC4; i += nblk * 256)
            __stcs(fill_ptr + i, mv);
    }
}

// ---------------------------------------------------------------------------
// Banded scores + softmax + attn@V — TI=16, interchanged QK loop,
// BAND-ONLY scores writes (mask prefilled by the QKV GEMM's fused tail).
// ---------------------------------------------------------------------------
#define TI    16
#define NUMAX 144
#define KVST  68
#define NT    256

__global__ __launch_bounds__(NT)
void scores_attn_kernel(const float* __restrict__ qkv,
                        float* __restrict__ scores_out,
                        __nv_bfloat16* __restrict__ attn_hi,
                        __nv_bfloat16* __restrict__ attn_lo)
{
    __shared__ float KVs[NUMAX * KVST];
    __shared__ float Qs[TI * KVST];
    __shared__ float Sc[TI * NUMAX];

    const int h  = blockIdx.y;
    const int i0 = blockIdx.x * TI;
    const int t  = threadIdx.x;

    const int j0 = max(0, i0 - KNB);
    const int j1 = min(S_ - 1, i0 + TI - 1 + KNB);
    const int NU = j1 - j0 + 1;           // <= 144

    const int hoff = h * DH_;

    for (int idx = t; idx < TI * 16; idx += NT) {
        int r = idx >> 4, dq = idx & 15;
        *(float4*)(Qs + r * KVST + dq * 4) =
            *(const float4*)(qkv + (size_t)(i0 + r) * E3_ + hoff + dq * 4);
    }
    for (int idx = t; idx < NU * 16; idx += NT) {
        int u = idx >> 4, dq = idx & 15;
        *(float4*)(KVs + u * KVST + dq * 4) =
            *(const float4*)(qkv + (size_t)(j0 + u) * E3_ + E_ + hoff + dq * 4);
    }
    __syncthreads();

    // scores: thread t owns key column u=t; dq outer, K row in regs
    if (t < NU) {
        const int j = j0 + t;
        const float4* kv4 = (const float4*)(KVs + t * KVST);
        float acc[TI];
#pragma unroll
        for (int r = 0; r < TI; r++) acc[r] = 0.f;
#pragma unroll
        for (int dq = 0; dq < 16; dq++) {
            const float4 b = kv4[dq];
#pragma unroll
            for (int r = 0; r < TI; r++) {
                const float4 a = *(const float4*)(Qs + r * KVST + dq * 4);
                acc[r] = fmaf(a.x, b.x, acc[r]);
                acc[r] = fmaf(a.y, b.y, acc[r]);
                acc[r] = fmaf(a.z, b.z, acc[r]);
                acc[r] = fmaf(a.w, b.w, acc[r]);
            }
        }
#pragma unroll
        for (int r = 0; r < TI; r++) {
            const int i = i0 + r;
            Sc[r * NUMAX + t] =
                (abs(i - j) <= KNB) ? acc[r] * 0.125f : -INFINITY;
        }
    }
    __syncthreads();

    // V band load (K dead) — overlaps the band stores
    for (int idx = t; idx < NU * 16; idx += NT) {
        int u = idx >> 4, dq = idx & 15;
        *(float4*)(KVs + u * KVST + dq * 4) =
            *(const float4*)(qkv + (size_t)(j0 + u) * E3_ + 2 * E_ + hoff + dq * 4);
    }

    // BAND-ONLY scores writes (mask region prefilled with MASKV)
#pragma unroll
    for (int r = 0; r < TI; r++) {
        const int i = i0 + r;
        const int lo = max(0, i - KNB), hi = min(S_ - 1, i + KNB);
        float* rowp = scores_out + ((size_t)h * S_ + i) * S_;
        for (int j = lo + t; j <= hi; j += NT)
            __stcs(rowp + j, Sc[r * NUMAX + (j - j0)]);
    }
    __syncthreads();   // Sc raw-value reads done before in-place softmax

    // softmax in place: warp w handles rows 2w, 2w+1
    const int w = t >> 5, lane = t & 31;
#pragma unroll
    for (int rr = 0; rr < 2; rr++) {
        const int r = w * 2 + rr;
        float m = -INFINITY;
        for (int u = lane; u < NU; u += 32)
            m = fmaxf(m, Sc[r * NUMAX + u]);
#pragma unroll
        for (int o = 16; o; o >>= 1)
            m = fmaxf(m, __shfl_xor_sync(0xFFFFFFFFu, m, o));
        float ssum = 0.f;
        for (int u = lane; u < NU; u += 32) {
            float e = expf(Sc[r * NUMAX + u] - m);
            Sc[r * NUMAX + u] = e;
            ssum += e;
        }
#pragma unroll
        for (int o = 16; o; o >>= 1)
            ssum += __shfl_xor_sync(0xFFFFFFFFu, ssum, o);
        float inv = 1.f / ssum;
        for (int u = lane; u < NU; u += 32)
            Sc[r * NUMAX + u] *= inv;
    }
    __syncthreads();

    // attn @ V (float4): all 256 threads, thread owns (row r, 4 d-cols)
    {
        const int r  = t >> 4;
        const int dg = t & 15;
        const float* pr = Sc + r * NUMAX;
        float4 acc = make_float4(0.f, 0.f, 0.f, 0.f);
        for (int u = 0; u < NU; u++) {
            const float p = pr[u];
            const float4 v = *(const float4*)(KVs + u * KVST + dg * 4);
            acc.x = fmaf(p, v.x, acc.x);
            acc.y = fmaf(p, v.y, acc.y);
            acc.z = fmaf(p, v.z, acc.z);
            acc.w = fmaf(p, v.w, acc.w);
        }
        __nv_bfloat162 h01 = __float22bfloat162_rn(make_float2(acc.x, acc.y));
        __nv_bfloat162 h23 = __float22bfloat162_rn(make_float2(acc.z, acc.w));
        float2 f01 = __bfloat1622float2(h01);
        float2 f23 = __bfloat1622float2(h23);
        __nv_bfloat162 l01 = __float22bfloat162_rn(make_float2(acc.x - f01.x, acc.y - f01.y));
        __nv_bfloat162 l23 = __float22bfloat162_rn(make_float2(acc.z - f23.x, acc.w - f23.y));
        const size_t idx = (size_t)(i0 + r) * E_ + hoff + dg * 4;
        uint2 hv, lv;
        hv.x = *(uint32_t*)&h01; hv.y = *(uint32_t*)&h23;
        lv.x = *(uint32_t*)&l01; lv.y = *(uint32_t*)&l23;
        *(uint2*)(attn_hi + idx) = hv;
        *(uint2*)(attn_lo + idx) = lv;
    }
}

// ---------------------------------------------------------------------------
// launch (single stream)
// ---------------------------------------------------------------------------
extern "C" void kernel_launch(void* const* d_in, const int* in_sizes, int n_in,
                              void* d_out, int out_size)
{
    const float* x     = (const float*)d_in[0];
    const float* W_qkv = (const float*)d_in[1];
    const float* b_qkv = (const float*)d_in[2];
    const float* W_out = (const float*)d_in[3];
    const float* b_out = (const float*)d_in[4];

    float* out_ptr    = (float*)d_out;
    float* scores_ptr = out_ptr + (size_t)S_ * E_;

    float* qkv_p;
    __nv_bfloat16 *xh, *xl, *wqh, *wql, *woh, *wol, *ah, *al;
    cudaGetSymbolAddress((void**)&qkv_p, g_qkv);
    cudaGetSymbolAddress((void**)&xh,  g_xh);
    cudaGetSymbolAddress((void**)&xl,  g_xl);
    cudaGetSymbolAddress((void**)&wqh, g_wqh);
    cudaGetSymbolAddress((void**)&wql, g_wql);
    cudaGetSymbolAddress((void**)&woh, g_woh);
    cudaGetSymbolAddress((void**)&wol, g_wol);
    cudaGetSymbolAddress((void**)&ah,  g_ah);
    cudaGetSymbolAddress((void**)&al,  g_al);

    cudaFuncSetAttribute(bf16s_gemm_nt_bias,
                         cudaFuncAttributeMaxDynamicSharedMemorySize, GSMEM);

    // fused splits
    split_all<<<(NSPLIT4 + 255) / 256, 256>>>(
        (const float4*)x, (const float4*)W_qkv, (const float4*)W_out,
        (uint2*)xh, (uint2*)xl, (uint2*)wqh, (uint2*)wql, (uint2*)woh, (uint2*)wol);

    // 1) QKV projection + fused scores mask fill
    {
        dim3 grid(E3_ / 64, S_ / 128);
        bf16s_gemm_nt_bias<<<grid, 256, GSMEM>>>(xh, xl, wqh, wql, b_qkv, qkv_p,
                                                 S_, E3_, E_, (float4*)scores_ptr);
    }

    // 2) banded scores (band-only writes) + softmax + attn@V
    {
        dim3 grid(S_ / TI, H_);
        scores_attn_kernel<<<grid, NT>>>(qkv_p, scores_ptr, ah, al);
    }

    // 3) output projection (no fill)
    {
        dim3 grid(E_ / 64, S_ / 128);
        bf16s_gemm_nt_bias<<<grid, 256, GSMEM>>>(ah, al, woh, wol, b_out, out_ptr,
                                                 S_, E_, E_, nullptr);
    }
}

// round 16
// speedup vs baseline: 1.3301x; 1.2990x over previous
#include <cuda_runtime.h>
#include <cuda_fp16.h>
#include <cstdint>
#include <math.h>

// Problem constants
#define S_   2048
#define E_   1024
#define H_   16
#define DH_  64
#define KNB  64
#define E3_  (3*E_)
#define MASKV (-1e10f)

// Scratch (__device__ globals)
__device__ float  g_qkv[(size_t)S_ * E3_];
__device__ __half g_xh[(size_t)S_ * E_];          // x, fp16 (1-term)
__device__ __half g_wqh[(size_t)E3_ * E_];        // W_qkv hi/lo fp16
__device__ __half g_wql[(size_t)E3_ * E_];
__device__ __half g_woh[(size_t)E_ * E_];         // W_out hi/lo fp16
__device__ __half g_wol[(size_t)E_ * E_];
__device__ __half g_ah[(size_t)S_ * E_];          // attn, fp16 (1-term)

// ---------------------------------------------------------------------------
// helpers
// ---------------------------------------------------------------------------
__device__ __forceinline__ uint32_t smem_u32(const void* p) {
    uint32_t a;
    asm("{ .reg .u64 t; cvta.to.shared.u64 t, %1; cvt.u32.u64 %0, t; }" : "=r"(a) : "l"(p));
    return a;
}
__device__ __forceinline__ uint32_t sw128(uint32_t off) {
    return off ^ ((off >> 3) & 0x70);
}
#define LDSM4(r, a) \
    asm volatile("ldmatrix.sync.aligned.m8n8.x4.shared.b16 {%0,%1,%2,%3}, [%4];" \
        : "=r"((r)[0]), "=r"((r)[1]), "=r"((r)[2]), "=r"((r)[3]) : "r"(a))

__device__ __forceinline__ void mma16816(float* d, const uint32_t* a, const uint32_t* b) {
    asm volatile("mma.sync.aligned.m16n8k16.row.col.f32.f16.f16.f32 "
        "{%0,%1,%2,%3}, {%4,%5,%6,%7}, {%8,%9}, {%0,%1,%2,%3};"
        : "+f"(d[0]), "+f"(d[1]), "+f"(d[2]), "+f"(d[3])
        : "r"(a[0]), "r"(a[1]), "r"(a[2]), "r"(a[3]), "r"(b[0]), "r"(b[1]));
}
#define CP_ASYNC16(dst, src) \
    asm volatile("cp.async.cg.shared.global [%0], [%1], 16;" :: "r"(dst), "l"(src))
#define CP_COMMIT() asm volatile("cp.async.commit_group;" ::: "memory")
#define CP_WAIT0()  asm volatile("cp.async.wait_group 0;" ::: "memory")

// ---------------------------------------------------------------------------
// fused conversion kernel:
//   x -> fp16 (hi only);  W_qkv, W_out -> fp16 hi + fp16 lo (2-term)
// ---------------------------------------------------------------------------
#define NX4  ((S_ * E_) / 4)
#define NWQ4 ((E3_ * E_) / 4)
#define NWO4 ((E_ * E_) / 4)
#define NSPLIT4 (NX4 + NWQ4 + NWO4)

__device__ __forceinline__ void splitw_one(const float4* in, uint2* hi, uint2* lo, int i) {
    float4 v = in[i];
    __half2 h0 = __floats2half2_rn(v.x, v.y);
    __half2 h1 = __floats2half2_rn(v.z, v.w);
    float2 f0 = __half22float2(h0);
    float2 f1 = __half22float2(h1);
    __half2 l0 = __floats2half2_rn(v.x - f0.x, v.y - f0.y);
    __half2 l1 = __floats2half2_rn(v.z - f1.x, v.w - f1.y);
    uint2 h, l;
    h.x = *(uint32_t*)&h0; h.y = *(uint32_t*)&h1;
    l.x = *(uint32_t*)&l0; l.y = *(uint32_t*)&l1;
    hi[i] = h;
    lo[i] = l;
}
__device__ __forceinline__ void cvt_one(const float4* in, uint2* hi, int i) {
    float4 v = in[i];
    __half2 h0 = __floats2half2_rn(v.x, v.y);
    __half2 h1 = __floats2half2_rn(v.z, v.w);
    uint2 h;
    h.x = *(uint32_t*)&h0; h.y = *(uint32_t*)&h1;
    hi[i] = h;
}

__global__ __launch_bounds__(256)
void split_all(const float4* __restrict__ x, const float4* __restrict__ wq,
               const float4* __restrict__ wo,
               uint2* __restrict__ xh,
               uint2* __restrict__ wqh, uint2* __restrict__ wql,
               uint2* __restrict__ woh, uint2* __restrict__ wol)
{
    int i = blockIdx.x * 256 + threadIdx.x;
    if (i < NX4) {
        cvt_one(x, xh, i);
    } else if (i < NX4 + NWQ4) {
        splitw_one(wq, wqh, wql, i - NX4);
    } else if (i < NSPLIT4) {
        splitw_one(wo, woh, wol, i - NX4 - NWQ4);
    }
}

// ---------------------------------------------------------------------------
// fp16 2-MMA tensor GEMM (NT): C[M,N] = A[M,K] @ (Bh+Bl)[N,K]^T + bias[N]
// A = fp16 1-term, B = fp16 2-term.  D = Ah*Bh + Ah*Bl.
// Tile 128x64x64, 256 threads, 2 CTAs/SM, double-buffered cp.async,
// single barrier per chunk, B-fragment double-buffer across ks.
// ---------------------------------------------------------------------------
#define ATILEB 16384                 // 128 x 64 fp16
#define BTILEB 8192                  // 64 x 64 fp16
#define STAGEB (ATILEB + 2 * BTILEB) // 32768
#define GSMEM  (2 * STAGEB)          // 65536

__global__ __launch_bounds__(256, 2)
void fp16_gemm_nt_bias(const __half* __restrict__ Ah,
                       const __half* __restrict__ Bh,
                       const __half* __restrict__ Bl,
                       const float* __restrict__ bias, float* __restrict__ C,
                       int M, int N, int K)
{
    extern __shared__ char sm[];
    const uint32_t sbase = smem_u32(sm);

    const int tid  = threadIdx.x;
    const int lane = tid & 31;
    const int wid  = tid >> 5;
    const int wm   = (wid & 3) * 32;
    const int wn   = (wid >> 2) * 32;
    const int m0   = blockIdx.y * 128;
    const int n0   = blockIdx.x * 64;

    const __half* abase    = Ah + (size_t)m0 * K;
    const __half* bbase[2] = { Bh + (size_t)n0 * K, Bl + (size_t)n0 * K };

    float d[2][4][4];
#pragma unroll
    for (int i = 0; i < 2; i++)
#pragma unroll
        for (int j = 0; j < 4; j++)
#pragma unroll
            for (int q = 0; q < 4; q++) d[i][j][q] = 0.f;

    auto issue = [&](int c) {
        const int s = c & 1;
        const int k0 = c * 64;
        const uint32_t sb = sbase + s * STAGEB;
        // A tile: 1024 chunks -> 4 per thread
#pragma unroll
        for (int l = 0; l < 4; l++) {
            const int idx = l * 256 + tid;
            const int row = idx >> 3;
            const int q   = idx & 7;
            const __half* src = abase + (size_t)row * K + k0 + q * 8;
            const uint32_t dst = sb + sw128(row * 128 + q * 16);
            CP_ASYNC16(dst, src);
        }
        // B tiles (hi, lo): 2 x 512 chunks -> 4 per thread
#pragma unroll
        for (int l = 0; l < 4; l++) {
            const int idx  = l * 256 + tid;
            const int tile = idx >> 9;
            const int w    = idx & 511;
            const int row  = w >> 3;
            const int q    = w & 7;
            const __half* src = bbase[tile] + (size_t)row * K + k0 + q * 8;
            const uint32_t dst = sb + ATILEB + tile * BTILEB
                               + sw128(row * 128 + q * 16);
            CP_ASYNC16(dst, src);
        }
        CP_COMMIT();
    };

    uint32_t baseA[2], baseB[2];
#pragma unroll
    for (int i = 0; i < 2; i++) {
        uint32_t ra = (uint32_t)(wm + i * 16 + (lane & 15));
        baseA[i] = (ra * 128) ^ ((ra * 16) & 0x70);
        uint32_t rb = (uint32_t)(wn + i * 16 + (lane & 15));
        baseB[i] = (rb * 128) ^ ((rb * 16) & 0x70);
    }
    const uint32_t lanecol = (uint32_t)((lane >> 4) << 4);

    auto loadB = [&](uint32_t sb, int ks, uint32_t (*bh)[2], uint32_t (*bl)[2]) {
        const uint32_t colb = (uint32_t)(ks * 32) ^ lanecol;
#pragma unroll
        for (int ng = 0; ng < 2; ng++) {
            uint32_t off = baseB[ng] ^ colb;
            uint32_t r[4];
            LDSM4(r, sb + ATILEB + off);
            bh[ng * 2 + 0][0] = r[0]; bh[ng * 2 + 0][1] = r[2];
            bh[ng * 2 + 1][0] = r[1]; bh[ng * 2 + 1][1] = r[3];
            LDSM4(r, sb + ATILEB + BTILEB + off);
            bl[ng * 2 + 0][0] = r[0]; bl[ng * 2 + 0][1] = r[2];
            bl[ng * 2 + 1][0] = r[1]; bl[ng * 2 + 1][1] = r[3];
        }
    };

    auto compute = [&](int s) {
        const uint32_t sb = sbase + s * STAGEB;
        uint32_t bh[2][4][2], bl[2][4][2];
        loadB(sb, 0, bh[0], bl[0]);
#pragma unroll
        for (int ks = 0; ks < 4; ks++) {
            const int cur = ks & 1;
            if (ks < 3) loadB(sb, ks + 1, bh[cur ^ 1], bl[cur ^ 1]);

            const uint32_t colb = (uint32_t)(ks * 32) ^ lanecol;
#pragma unroll
            for (int mt = 0; mt < 2; mt++) {
                uint32_t off = baseA[mt] ^ colb;
                uint32_t ah[4];
                LDSM4(ah, sb + off);
#pragma unroll
                for (int nt = 0; nt < 4; nt++) {
                    mma16816(d[mt][nt], ah, bh[cur][nt]);
                    mma16816(d[mt][nt], ah, bl[cur][nt]);
                }
            }
        }
    };

    const int NC = K / 64;
    issue(0);
    for (int c = 0; c < NC; c++) {
        CP_WAIT0();
        __syncthreads();
        if (c + 1 < NC) issue(c + 1);
        compute(c & 1);
    }

    // epilogue
#pragma unroll
    for (int mt = 0; mt < 2; mt++) {
        const int r0 = m0 + wm + mt * 16 + (lane >> 2);
#pragma unroll
        for (int nt = 0; nt < 4; nt++) {
            const int c0 = n0 + wn + nt * 8 + (lane & 3) * 2;
            const float b0 = bias[c0], b1 = bias[c0 + 1];
            float2 o;
            o.x = d[mt][nt][0] + b0;
            o.y = d[mt][nt][1] + b1;
            *(float2*)(C + (size_t)r0 * N + c0) = o;
            o.x = d[mt][nt][2] + b0;
            o.y = d[mt][nt][3] + b1;
            *(float2*)(C + (size_t)(r0 + 8) * N + c0) = o;
        }
    }
}

// ---------------------------------------------------------------------------
// Banded scores + softmax + attn@V — TI=16, interchanged QK loop (R13 proven),
// full masked-row float4 __stcs stores; attn emitted as fp16 (1-term).
// ---------------------------------------------------------------------------
#define TI    16
#define NUMAX 144
#define KVST  68
#define NT    256

__global__ __launch_bounds__(NT)
void scores_attn_kernel(const float* __restrict__ qkv,
                        float* __restrict__ scores_out,
                        __half* __restrict__ attn_h)
{
    __shared__ float KVs[NUMAX * KVST];
    __shared__ float Qs[TI * KVST];
    __shared__ float Sc[TI * NUMAX];

    const int h  = blockIdx.y;
    const int i0 = blockIdx.x * TI;
    const int t  = threadIdx.x;

    const int j0 = max(0, i0 - KNB);
    const int j1 = min(S_ - 1, i0 + TI - 1 + KNB);
    const int NU = j1 - j0 + 1;           // <= 144

    const int hoff = h * DH_;

    for (int idx = t; idx < TI * 16; idx += NT) {
        int r = idx >> 4, dq = idx & 15;
        *(float4*)(Qs + r * KVST + dq * 4) =
            *(const float4*)(qkv + (size_t)(i0 + r) * E3_ + hoff + dq * 4);
    }
    for (int idx = t; idx < NU * 16; idx += NT) {
        int u = idx >> 4, dq = idx & 15;
        *(float4*)(KVs + u * KVST + dq * 4) =
            *(const float4*)(qkv + (size_t)(j0 + u) * E3_ + E_ + hoff + dq * 4);
    }
    __syncthreads();

    // scores: thread t owns key column u=t; dq outer, K row in regs
    if (t < NU) {
        const int j = j0 + t;
        const float4* kv4 = (const float4*)(KVs + t * KVST);
        float acc[TI];
#pragma unroll
        for (int r = 0; r < TI; r++) acc[r] = 0.f;
#pragma unroll
        for (int dq = 0; dq < 16; dq++) {
            const float4 b = kv4[dq];
#pragma unroll
            for (int r = 0; r < TI; r++) {
                const float4 a = *(const float4*)(Qs + r * KVST + dq * 4);
                acc[r] = fmaf(a.x, b.x, acc[r]);
                acc[r] = fmaf(a.y, b.y, acc[r]);
                acc[r] = fmaf(a.z, b.z, acc[r]);
                acc[r] = fmaf(a.w, b.w, acc[r]);
            }
        }
#pragma unroll
        for (int r = 0; r < TI; r++) {
            const int i = i0 + r;
            Sc[r * NUMAX + t] =
                (abs(i - j) <= KNB) ? acc[r] * 0.125f : -INFINITY;
        }
    }
    __syncthreads();

    // V band load (K dead) — overlaps the large scores stores
    for (int idx = t; idx < NU * 16; idx += NT) {
        int u = idx >> 4, dq = idx & 15;
        *(float4*)(KVs + u * KVST + dq * 4) =
            *(const float4*)(qkv + (size_t)(j0 + u) * E3_ + 2 * E_ + hoff + dq * 4);
    }

    // masked scores rows -> gmem (streaming float4 stores)
#pragma unroll
    for (int r = 0; r < TI; r++) {
        const int i = i0 + r;
        const int lo = i - KNB, hi = i + KNB;
        float* rowp = scores_out + ((size_t)h * S_ + i) * S_;
#pragma unroll
        for (int it = 0; it < S_ / (NT * 4); it++) {
            const int j = (it * NT + t) * 4;
            float4 v;
            v.x = (j + 0 >= lo && j + 0 <= hi) ? Sc[r * NUMAX + (j + 0 - j0)] : MASKV;
            v.y = (j + 1 >= lo && j + 1 <= hi) ? Sc[r * NUMAX + (j + 1 - j0)] : MASKV;
            v.z = (j + 2 >= lo && j + 2 <= hi) ? Sc[r * NUMAX + (j + 2 - j0)] : MASKV;
            v.w = (j + 3 >= lo && j + 3 <= hi) ? Sc[r * NUMAX + (j + 3 - j0)] : MASKV;
            __stcs((float4*)(rowp + j), v);
        }
    }
    __syncthreads();   // Sc raw-value reads done before in-place softmax

    // softmax in place: warp w handles rows 2w, 2w+1
    const int w = t >> 5, lane = t & 31;
#pragma unroll
    for (int rr = 0; rr < 2; rr++) {
        const int r = w * 2 + rr;
        float m = -INFINITY;
        for (int u = lane; u < NU; u += 32)
            m = fmaxf(m, Sc[r * NUMAX + u]);
#pragma unroll
        for (int o = 16; o; o >>= 1)
            m = fmaxf(m, __shfl_xor_sync(0xFFFFFFFFu, m, o));
        float ssum = 0.f;
        for (int u = lane; u < NU; u += 32) {
            float e = expf(Sc[r * NUMAX + u] - m);
            Sc[r * NUMAX + u] = e;
            ssum += e;
        }
#pragma unroll
        for (int o = 16; o; o >>= 1)
            ssum += __shfl_xor_sync(0xFFFFFFFFu, ssum, o);
        float inv = 1.f / ssum;
        for (int u = lane; u < NU; u += 32)
            Sc[r * NUMAX + u] *= inv;
    }
    __syncthreads();

    // attn @ V (float4): all 256 threads, thread owns (row r, 4 d-cols)
    {
        const int r  = t >> 4;
        const int dg = t & 15;
        const float* pr = Sc + r * NUMAX;
        float4 acc = make_float4(0.f, 0.f, 0.f, 0.f);
        for (int u = 0; u < NU; u++) {
            const float p = pr[u];
            const float4 v = *(const float4*)(KVs + u * KVST + dg * 4);
            acc.x = fmaf(p, v.x, acc.x);
            acc.y = fmaf(p, v.y, acc.y);
            acc.z = fmaf(p, v.z, acc.z);
            acc.w = fmaf(p, v.w, acc.w);
        }
        __half2 p01 = __floats2half2_rn(acc.x, acc.y);
        __half2 p23 = __floats2half2_rn(acc.z, acc.w);
        uint2 hv;
        hv.x = *(uint32_t*)&p01; hv.y = *(uint32_t*)&p23;
        const size_t idx = (size_t)(i0 + r) * E_ + hoff + dg * 4;
        *(uint2*)(attn_h + idx) = hv;
    }
}

// ---------------------------------------------------------------------------
// launch (single stream)
// ---------------------------------------------------------------------------
extern "C" void kernel_launch(void* const* d_in, const int* in_sizes, int n_in,
                              void* d_out, int out_size)
{
    const float* x     = (const float*)d_in[0];
    const float* W_qkv = (const float*)d_in[1];
    const float* b_qkv = (const float*)d_in[2];
    const float* W_out = (const float*)d_in[3];
    const float* b_out = (const float*)d_in[4];

    float* out_ptr    = (float*)d_out;
    float* scores_ptr = out_ptr + (size_t)S_ * E_;

    float* qkv_p;
    __half *xh, *wqh, *wql, *woh, *wol, *ah;
    cudaGetSymbolAddress((void**)&qkv_p, g_qkv);
    cudaGetSymbolAddress((void**)&xh,  g_xh);
    cudaGetSymbolAddress((void**)&wqh, g_wqh);
    cudaGetSymbolAddress((void**)&wql, g_wql);
    cudaGetSymbolAddress((void**)&woh, g_woh);
    cudaGetSymbolAddress((void**)&wol, g_wol);
    cudaGetSymbolAddress((void**)&ah,  g_ah);

    cudaFuncSetAttribute(fp16_gemm_nt_bias,
                         cudaFuncAttributeMaxDynamicSharedMemorySize, GSMEM);

    // fused conversions
    split_all<<<(NSPLIT4 + 255) / 256, 256>>>(
        (const float4*)x, (const float4*)W_qkv, (const float4*)W_out,
        (uint2*)xh, (uint2*)wqh, (uint2*)wql, (uint2*)woh, (uint2*)wol);

    // 1) QKV projection
    {
        dim3 grid(E3_ / 64, S_ / 128);
        fp16_gemm_nt_bias<<<grid, 256, GSMEM>>>(xh, wqh, wql, b_qkv, qkv_p,
                                                S_, E3_, E_);
    }

    // 2) banded scores + softmax + attn@V
    {
        dim3 grid(S_ / TI, H_);
        scores_attn_kernel<<<grid, NT>>>(qkv_p, scores_ptr, ah);
    }

    // 3) output projection
    {
        dim3 grid(E_ / 64, S_ / 128);
        fp16_gemm_nt_bias<<<grid, 256, GSMEM>>>(ah, woh, wol, b_out, out_ptr,
                                                S_, E_, E_);
    }
}

// round 17
// speedup vs baseline: 1.3307x; 1.0005x over previous
#include <cuda_runtime.h>
#include <cuda_fp16.h>
#include <cstdint>
#include <math.h>

// Problem constants
#define S_   2048
#define E_   1024
#define H_   16
#define DH_  64
#define KNB  64
#define E3_  (3*E_)
#define MASKV (-1e10f)

// Scratch (__device__ globals)
__device__ float  g_qkv[(size_t)S_ * E3_];
__device__ __half g_xh[(size_t)S_ * E_];          // x, fp16 (1-term)
__device__ __half g_wqh[(size_t)E3_ * E_];        // W_qkv hi/lo fp16
__device__ __half g_wql[(size_t)E3_ * E_];
__device__ __half g_woh[(size_t)E_ * E_];         // W_out hi/lo fp16
__device__ __half g_wol[(size_t)E_ * E_];
__device__ __half g_ah[(size_t)S_ * E_];          // attn, fp16 (1-term)

// ---------------------------------------------------------------------------
// helpers
// ---------------------------------------------------------------------------
__device__ __forceinline__ uint32_t smem_u32(const void* p) {
    uint32_t a;
    asm("{ .reg .u64 t; cvta.to.shared.u64 t, %1; cvt.u32.u64 %0, t; }" : "=r"(a) : "l"(p));
    return a;
}
__device__ __forceinline__ uint32_t sw128(uint32_t off) {
    return off ^ ((off >> 3) & 0x70);
}
#define LDSM4(r, a) \
    asm volatile("ldmatrix.sync.aligned.m8n8.x4.shared.b16 {%0,%1,%2,%3}, [%4];" \
        : "=r"((r)[0]), "=r"((r)[1]), "=r"((r)[2]), "=r"((r)[3]) : "r"(a))

__device__ __forceinline__ void mma16816(float* d, const uint32_t* a, const uint32_t* b) {
    asm volatile("mma.sync.aligned.m16n8k16.row.col.f32.f16.f16.f32 "
        "{%0,%1,%2,%3}, {%4,%5,%6,%7}, {%8,%9}, {%0,%1,%2,%3};"
        : "+f"(d[0]), "+f"(d[1]), "+f"(d[2]), "+f"(d[3])
        : "r"(a[0]), "r"(a[1]), "r"(a[2]), "r"(a[3]), "r"(b[0]), "r"(b[1]));
}
#define CP_ASYNC16(dst, src) \
    asm volatile("cp.async.cg.shared.global [%0], [%1], 16;" :: "r"(dst), "l"(src))
#define CP_COMMIT() asm volatile("cp.async.commit_group;" ::: "memory")
#define CP_WAIT0()  asm volatile("cp.async.wait_group 0;" ::: "memory")

// ---------------------------------------------------------------------------
// fused conversion kernel:
//   x -> fp16 (hi only);  W_qkv, W_out -> fp16 hi + fp16 lo (2-term)
// ---------------------------------------------------------------------------
#define NX4  ((S_ * E_) / 4)
#define NWQ4 ((E3_ * E_) / 4)
#define NWO4 ((E_ * E_) / 4)
#define NSPLIT4 (NX4 + NWQ4 + NWO4)

__device__ __forceinline__ void splitw_one(const float4* in, uint2* hi, uint2* lo, int i) {
    float4 v = in[i];
    __half2 h0 = __floats2half2_rn(v.x, v.y);
    __half2 h1 = __floats2half2_rn(v.z, v.w);
    float2 f0 = __half22float2(h0);
    float2 f1 = __half22float2(h1);
    __half2 l0 = __floats2half2_rn(v.x - f0.x, v.y - f0.y);
    __half2 l1 = __floats2half2_rn(v.z - f1.x, v.w - f1.y);
    uint2 h, l;
    h.x = *(uint32_t*)&h0; h.y = *(uint32_t*)&h1;
    l.x = *(uint32_t*)&l0; l.y = *(uint32_t*)&l1;
    hi[i] = h;
    lo[i] = l;
}
__device__ __forceinline__ void cvt_one(const float4* in, uint2* hi, int i) {
    float4 v = in[i];
    __half2 h0 = __floats2half2_rn(v.x, v.y);
    __half2 h1 = __floats2half2_rn(v.z, v.w);
    uint2 h;
    h.x = *(uint32_t*)&h0; h.y = *(uint32_t*)&h1;
    hi[i] = h;
}

__global__ __launch_bounds__(256)
void split_all(const float4* __restrict__ x, const float4* __restrict__ wq,
               const float4* __restrict__ wo,
               uint2* __restrict__ xh,
               uint2* __restrict__ wqh, uint2* __restrict__ wql,
               uint2* __restrict__ woh, uint2* __restrict__ wol)
{
    int i = blockIdx.x * 256 + threadIdx.x;
    if (i < NX4) {
        cvt_one(x, xh, i);
    } else if (i < NX4 + NWQ4) {
        splitw_one(wq, wqh, wql, i - NX4);
    } else if (i < NSPLIT4) {
        splitw_one(wo, woh, wol, i - NX4 - NWQ4);
    }
}

// ---------------------------------------------------------------------------
// fp16 2-MMA tensor GEMM (NT): C[M,N] = A[M,K] @ (Bh+Bl)[N,K]^T + bias[N]
// A = fp16 1-term, B = fp16 2-term.  D = Ah*Bh + Ah*Bl.
// Tile 128x64x64, 256 threads, 2 CTAs/SM, double-buffered cp.async,
// single barrier per chunk, A+B fragment double-buffer across ks.
// ---------------------------------------------------------------------------
#define ATILEB 16384                 // 128 x 64 fp16
#define BTILEB 8192                  // 64 x 64 fp16
#define STAGEB (ATILEB + 2 * BTILEB) // 32768
#define GSMEM  (2 * STAGEB)          // 65536

__global__ __launch_bounds__(256, 2)
void fp16_gemm_nt_bias(const __half* __restrict__ Ah,
                       const __half* __restrict__ Bh,
                       const __half* __restrict__ Bl,
                       const float* __restrict__ bias, float* __restrict__ C,
                       int M, int N, int K)
{
    extern __shared__ char sm[];
    const uint32_t sbase = smem_u32(sm);

    const int tid  = threadIdx.x;
    const int lane = tid & 31;
    const int wid  = tid >> 5;
    const int wm   = (wid & 3) * 32;
    const int wn   = (wid >> 2) * 32;
    const int m0   = blockIdx.y * 128;
    const int n0   = blockIdx.x * 64;

    const __half* abase    = Ah + (size_t)m0 * K;
    const __half* bbase[2] = { Bh + (size_t)n0 * K, Bl + (size_t)n0 * K };

    float d[2][4][4];
#pragma unroll
    for (int i = 0; i < 2; i++)
#pragma unroll
        for (int j = 0; j < 4; j++)
#pragma unroll
            for (int q = 0; q < 4; q++) d[i][j][q] = 0.f;

    auto issue = [&](int c) {
        const int s = c & 1;
        const int k0 = c * 64;
        const uint32_t sb = sbase + s * STAGEB;
        // A tile: 1024 chunks -> 4 per thread
#pragma unroll
        for (int l = 0; l < 4; l++) {
            const int idx = l * 256 + tid;
            const int row = idx >> 3;
            const int q   = idx & 7;
            const __half* src = abase + (size_t)row * K + k0 + q * 8;
            const uint32_t dst = sb + sw128(row * 128 + q * 16);
            CP_ASYNC16(dst, src);
        }
        // B tiles (hi, lo): 2 x 512 chunks -> 4 per thread
#pragma unroll
        for (int l = 0; l < 4; l++) {
            const int idx  = l * 256 + tid;
            const int tile = idx >> 9;
            const int w    = idx & 511;
            const int row  = w >> 3;
            const int q    = w & 7;
            const __half* src = bbase[tile] + (size_t)row * K + k0 + q * 8;
            const uint32_t dst = sb + ATILEB + tile * BTILEB
                               + sw128(row * 128 + q * 16);
            CP_ASYNC16(dst, src);
        }
        CP_COMMIT();
    };

    uint32_t baseA[2], baseB[2];
#pragma unroll
    for (int i = 0; i < 2; i++) {
        uint32_t ra = (uint32_t)(wm + i * 16 + (lane & 15));
        baseA[i] = (ra * 128) ^ ((ra * 16) & 0x70);
        uint32_t rb = (uint32_t)(wn + i * 16 + (lane & 15));
        baseB[i] = (rb * 128) ^ ((rb * 16) & 0x70);
    }
    const uint32_t lanecol = (uint32_t)((lane >> 4) << 4);

    // fragment loaders for one ks into the given buffers
    auto loadB = [&](uint32_t sb, int ks, uint32_t (*bh)[2], uint32_t (*bl)[2]) {
        const uint32_t colb = (uint32_t)(ks * 32) ^ lanecol;
#pragma unroll
        for (int ng = 0; ng < 2; ng++) {
            uint32_t off = baseB[ng] ^ colb;
            uint32_t r[4];
            LDSM4(r, sb + ATILEB + off);
            bh[ng * 2 + 0][0] = r[0]; bh[ng * 2 + 0][1] = r[2];
            bh[ng * 2 + 1][0] = r[1]; bh[ng * 2 + 1][1] = r[3];
            LDSM4(r, sb + ATILEB + BTILEB + off);
            bl[ng * 2 + 0][0] = r[0]; bl[ng * 2 + 0][1] = r[2];
            bl[ng * 2 + 1][0] = r[1]; bl[ng * 2 + 1][1] = r[3];
        }
    };
    auto loadA = [&](uint32_t sb, int ks, uint32_t (*ah)[4]) {
        const uint32_t colb = (uint32_t)(ks * 32) ^ lanecol;
#pragma unroll
        for (int mt = 0; mt < 2; mt++) {
            uint32_t off = baseA[mt] ^ colb;
            LDSM4(ah[mt], sb + off);
        }
    };

    auto compute = [&](int s) {
        const uint32_t sb = sbase + s * STAGEB;
        uint32_t ah[2][2][4];
        uint32_t bh[2][4][2], bl[2][4][2];
        loadA(sb, 0, ah[0]);
        loadB(sb, 0, bh[0], bl[0]);
#pragma unroll
        for (int ks = 0; ks < 4; ks++) {
            const int cur = ks & 1;
            if (ks < 3) {
                loadA(sb, ks + 1, ah[cur ^ 1]);
                loadB(sb, ks + 1, bh[cur ^ 1], bl[cur ^ 1]);
            }
#pragma unroll
            for (int mt = 0; mt < 2; mt++) {
#pragma unroll
                for (int nt = 0; nt < 4; nt++) {
                    mma16816(d[mt][nt], ah[cur][mt], bh[cur][nt]);
                    mma16816(d[mt][nt], ah[cur][mt], bl[cur][nt]);
                }
            }
        }
    };

    const int NC = K / 64;
    issue(0);
    for (int c = 0; c < NC; c++) {
        CP_WAIT0();
        __syncthreads();
        if (c + 1 < NC) issue(c + 1);
        compute(c & 1);
    }

    // epilogue
#pragma unroll
    for (int mt = 0; mt < 2; mt++) {
        const int r0 = m0 + wm + mt * 16 + (lane >> 2);
#pragma unroll
        for (int nt = 0; nt < 4; nt++) {
            const int c0 = n0 + wn + nt * 8 + (lane & 3) * 2;
            const float b0 = bias[c0], b1 = bias[c0 + 1];
            float2 o;
            o.x = d[mt][nt][0] + b0;
            o.y = d[mt][nt][1] + b1;
            *(float2*)(C + (size_t)r0 * N + c0) = o;
            o.x = d[mt][nt][2] + b0;
            o.y = d[mt][nt][3] + b1;
            *(float2*)(C + (size_t)(r0 + 8) * N + c0) = o;
        }
    }
}

// ---------------------------------------------------------------------------
// Banded scores + softmax + attn@V — TI=16, interchanged QK loop (proven),
// full masked-row float4 __stcs stores; attn emitted as fp16 (1-term).
// ---------------------------------------------------------------------------
#define TI    16
#define NUMAX 144
#define KVST  68
#define NT    256

__global__ __launch_bounds__(NT)
void scores_attn_kernel(const float* __restrict__ qkv,
                        float* __restrict__ scores_out,
                        __half* __restrict__ attn_h)
{
    __shared__ float KVs[NUMAX * KVST];
    __shared__ float Qs[TI * KVST];
    __shared__ float Sc[TI * NUMAX];

    const int h  = blockIdx.y;
    const int i0 = blockIdx.x * TI;
    const int t  = threadIdx.x;

    const int j0 = max(0, i0 - KNB);
    const int j1 = min(S_ - 1, i0 + TI - 1 + KNB);
    const int NU = j1 - j0 + 1;           // <= 144

    const int hoff = h * DH_;

    for (int idx = t; idx < TI * 16; idx += NT) {
        int r = idx >> 4, dq = idx & 15;
        *(float4*)(Qs + r * KVST + dq * 4) =
            *(const float4*)(qkv + (size_t)(i0 + r) * E3_ + hoff + dq * 4);
    }
    for (int idx = t; idx < NU * 16; idx += NT) {
        int u = idx >> 4, dq = idx & 15;
        *(float4*)(KVs + u * KVST + dq * 4) =
            *(const float4*)(qkv + (size_t)(j0 + u) * E3_ + E_ + hoff + dq * 4);
    }
    __syncthreads();

    // scores: thread t owns key column u=t; dq outer, K row in regs
    if (t < NU) {
        const int j = j0 + t;
        const float4* kv4 = (const float4*)(KVs + t * KVST);
        float acc[TI];
#pragma unroll
        for (int r = 0; r < TI; r++) acc[r] = 0.f;
#pragma unroll
        for (int dq = 0; dq < 16; dq++) {
            const float4 b = kv4[dq];
#pragma unroll
            for (int r = 0; r < TI; r++) {
                const float4 a = *(const float4*)(Qs + r * KVST + dq * 4);
                acc[r] = fmaf(a.x, b.x, acc[r]);
                acc[r] = fmaf(a.y, b.y, acc[r]);
                acc[r] = fmaf(a.z, b.z, acc[r]);
                acc[r] = fmaf(a.w, b.w, acc[r]);
            }
        }
#pragma unroll
        for (int r = 0; r < TI; r++) {
            const int i = i0 + r;
            Sc[r * NUMAX + t] =
                (abs(i - j) <= KNB) ? acc[r] * 0.125f : -INFINITY;
        }
    }
    __syncthreads();

    // V band load (K dead) — overlaps the large scores stores
    for (int idx = t; idx < NU * 16; idx += NT) {
        int u = idx >> 4, dq = idx & 15;
        *(float4*)(KVs + u * KVST + dq * 4) =
            *(const float4*)(qkv + (size_t)(j0 + u) * E3_ + 2 * E_ + hoff + dq * 4);
    }

    // masked scores rows -> gmem (streaming float4 stores)
#pragma unroll
    for (int r = 0; r < TI; r++) {
        const int i = i0 + r;
        const int lo = i - KNB, hi = i + KNB;
        float* rowp = scores_out + ((size_t)h * S_ + i) * S_;
#pragma unroll
        for (int it = 0; it < S_ / (NT * 4); it++) {
            const int j = (it * NT + t) * 4;
            float4 v;
            v.x = (j + 0 >= lo && j + 0 <= hi) ? Sc[r * NUMAX + (j + 0 - j0)] : MASKV;
            v.y = (j + 1 >= lo && j + 1 <= hi) ? Sc[r * NUMAX + (j + 1 - j0)] : MASKV;
            v.z = (j + 2 >= lo && j + 2 <= hi) ? Sc[r * NUMAX + (j + 2 - j0)] : MASKV;
            v.w = (j + 3 >= lo && j + 3 <= hi) ? Sc[r * NUMAX + (j + 3 - j0)] : MASKV;
            __stcs((float4*)(rowp + j), v);
        }
    }
    __syncthreads();   // Sc raw-value reads done before in-place softmax

    // softmax in place: warp w handles rows 2w, 2w+1
    const int w = t >> 5, lane = t & 31;
#pragma unroll
    for (int rr = 0; rr < 2; rr++) {
        const int r = w * 2 + rr;
        float m = -INFINITY;
        for (int u = lane; u < NU; u += 32)
            m = fmaxf(m, Sc[r * NUMAX + u]);
#pragma unroll
        for (int o = 16; o; o >>= 1)
            m = fmaxf(m, __shfl_xor_sync(0xFFFFFFFFu, m, o));
        float ssum = 0.f;
        for (int u = lane; u < NU; u += 32) {
            float e = expf(Sc[r * NUMAX + u] - m);
            Sc[r * NUMAX + u] = e;
            ssum += e;
        }
#pragma unroll
        for (int o = 16; o; o >>= 1)
            ssum += __shfl_xor_sync(0xFFFFFFFFu, ssum, o);
        float inv = 1.f / ssum;
        for (int u = lane; u < NU; u += 32)
            Sc[r * NUMAX + u] *= inv;
    }
    __syncthreads();

    // attn @ V (float4): all 256 threads, thread owns (row r, 4 d-cols)
    {
        const int r  = t >> 4;
        const int dg = t & 15;
        const float* pr = Sc + r * NUMAX;
        float4 acc = make_float4(0.f, 0.f, 0.f, 0.f);
        for (int u = 0; u < NU; u++) {
            const float p = pr[u];
            const float4 v = *(const float4*)(KVs + u * KVST + dg * 4);
            acc.x = fmaf(p, v.x, acc.x);
            acc.y = fmaf(p, v.y, acc.y);
            acc.z = fmaf(p, v.z, acc.z);
            acc.w = fmaf(p, v.w, acc.w);
        }
        __half2 p01 = __floats2half2_rn(acc.x, acc.y);
        __half2 p23 = __floats2half2_rn(acc.z, acc.w);
        uint2 hv;
        hv.x = *(uint32_t*)&p01; hv.y = *(uint32_t*)&p23;
        const size_t idx = (size_t)(i0 + r) * E_ + hoff + dg * 4;
        *(uint2*)(attn_h + idx) = hv;
    }
}

// ---------------------------------------------------------------------------
// launch (single stream)
// ---------------------------------------------------------------------------
extern "C" void kernel_launch(void* const* d_in, const int* in_sizes, int n_in,
                              void* d_out, int out_size)
{
    const float* x     = (const float*)d_in[0];
    const float* W_qkv = (const float*)d_in[1];
    const float* b_qkv = (const float*)d_in[2];
    const float* W_out = (const float*)d_in[3];
    const float* b_out = (const float*)d_in[4];

    float* out_ptr    = (float*)d_out;
    float* scores_ptr = out_ptr + (size_t)S_ * E_;

    float* qkv_p;
    __half *xh, *wqh, *wql, *woh, *wol, *ah;
    cudaGetSymbolAddress((void**)&qkv_p, g_qkv);
    cudaGetSymbolAddress((void**)&xh,  g_xh);
    cudaGetSymbolAddress((void**)&wqh, g_wqh);
    cudaGetSymbolAddress((void**)&wql, g_wql);
    cudaGetSymbolAddress((void**)&woh, g_woh);
    cudaGetSymbolAddress((void**)&wol, g_wol);
    cudaGetSymbolAddress((void**)&ah,  g_ah);

    cudaFuncSetAttribute(fp16_gemm_nt_bias,
                         cudaFuncAttributeMaxDynamicSharedMemorySize, GSMEM);

    // fused conversions
    split_all<<<(NSPLIT4 + 255) / 256, 256>>>(
        (const float4*)x, (const float4*)W_qkv, (const float4*)W_out,
        (uint2*)xh, (uint2*)wqh, (uint2*)wql, (uint2*)woh, (uint2*)wol);

    // 1) QKV projection
    {
        dim3 grid(E3_ / 64, S_ / 128);
        fp16_gemm_nt_bias<<<grid, 256, GSMEM>>>(xh, wqh, wql, b_qkv, qkv_p,
                                                S_, E3_, E_);
    }

    // 2) banded scores + softmax + attn@V
    {
        dim3 grid(S_ / TI, H_);
        scores_attn_kernel<<<grid, NT>>>(qkv_p, scores_ptr, ah);
    }

    // 3) output projection
    {
        dim3 grid(E_ / 64, S_ / 128);
        fp16_gemm_nt_bias<<<grid, 256, GSMEM>>>(ah, woh, wol, b_out, out_ptr,
                                                S_, E_, E_);
    }
}